// round 5
// baseline (speedup 1.0000x reference)
#include <cuda_runtime.h>
#include <math.h>

// Problem constants
#define NB 128
#define NI 1152
#define NO 32
#define ND 16
#define KSUB 922          // ceil(0.8 * 1152)
#define CHUNKS 18
#define IPB (NI / CHUNKS) // 64 i's per block
#define IPW (IPB / 8)     // 8 i's per warp (8 warps / block)
#define MAXREJ 232        // >= NI - KSUB = 230

// Scratch (no allocation allowed -> __device__ globals)
__device__ float g_num[NB * NO * ND];
__device__ float g_den[NB * NO];
__device__ float g_losses[(size_t)NB * NO * NI]; // transposed: [b][o][i]

__global__ void k_zero() {
    int idx = blockIdx.x * blockDim.x + threadIdx.x;
    if (idx < NB * NO * ND) g_num[idx] = 0.f;
    if (idx < NB * NO)      g_den[idx] = 0.f;
}

// ---------------------------------------------------------------------------
// Pass 1: n = ||u||, num = sum_i u*n, den = sum_i n  (per b,o)
// One warp per (b,i); lane = o. Each lane reads its 64B capsule (4x LDG.128).
// ---------------------------------------------------------------------------
__global__ void __launch_bounds__(256) k_pass1(const float* __restrict__ u) {
    int b = blockIdx.x / CHUNKS;
    int chunk = blockIdx.x % CHUNKS;
    int w = threadIdx.x >> 5;
    int lane = threadIdx.x & 31;

    const float4* up = (const float4*)u + (size_t)b * NI * (NO * ND / 4);
    float acc[ND];
    float accden = 0.f;
#pragma unroll
    for (int d = 0; d < ND; d++) acc[d] = 0.f;

    int i0 = chunk * IPB + w * IPW;
#pragma unroll
    for (int ii = 0; ii < IPW; ii++) {
        const float4* row = up + (size_t)(i0 + ii) * (NO * ND / 4) + lane * (ND / 4);
        float4 a0 = row[0], a1 = row[1], a2 = row[2], a3 = row[3];
        float va[16] = {a0.x, a0.y, a0.z, a0.w, a1.x, a1.y, a1.z, a1.w,
                        a2.x, a2.y, a2.z, a2.w, a3.x, a3.y, a3.z, a3.w};
        float s = 0.f;
#pragma unroll
        for (int d = 0; d < 16; d++) s += va[d] * va[d];
        float n = sqrtf(s);
#pragma unroll
        for (int d = 0; d < 16; d++) acc[d] += va[d] * n;
        accden += n;
    }

    __shared__ float snum[8][NO * ND];
    __shared__ float sden[8][NO];
#pragma unroll
    for (int d = 0; d < ND; d++) snum[w][d * NO + lane] = acc[d];
    sden[w][lane] = accden;
    __syncthreads();

    for (int idx = threadIdx.x; idx < NO * ND; idx += 256) {
        int d = idx / NO, o = idx % NO;
        float s = 0.f;
#pragma unroll
        for (int ww = 0; ww < 8; ww++) s += snum[ww][idx];
        atomicAdd(&g_num[b * NO * ND + o * ND + d], s);
    }
    if (threadIdx.x < NO) {
        float s = 0.f;
#pragma unroll
        for (int ww = 0; ww < 8; ww++) s += sden[ww][threadIdx.x];
        atomicAdd(&g_den[b * NO + threadIdx.x], s);
    }
}

// ---------------------------------------------------------------------------
// Pass 2: losses[b,o,i] = -<v[b,o,:], u[b,i,o,:]>, v computed in-kernel.
// Stores TRANSPOSED [b][o][i] via padded smem tile for coalesced select reads.
// ---------------------------------------------------------------------------
__global__ void __launch_bounds__(256) k_pass2(const float* __restrict__ u) {
    __shared__ float sv[ND * NO];        // transposed: sv[d*NO + o]
    __shared__ float tile[IPB][NO + 1];  // [i_local][o], padded
    int b = blockIdx.x / CHUNKS;
    int chunk = blockIdx.x % CHUNKS;
    for (int idx = threadIdx.x; idx < NO * ND; idx += 256) {
        int o = idx / ND, d = idx % ND;
        sv[d * NO + o] = g_num[b * NO * ND + idx] / g_den[b * NO + o];
    }
    __syncthreads();

    int w = threadIdx.x >> 5;
    int lane = threadIdx.x & 31;
    const float4* up = (const float4*)u + (size_t)b * NI * (NO * ND / 4);
    int i0 = chunk * IPB;
#pragma unroll
    for (int ii = 0; ii < IPW; ii++) {
        int il = w * IPW + ii;
        const float4* row = up + (size_t)(i0 + il) * (NO * ND / 4) + lane * (ND / 4);
        float4 a0 = row[0], a1 = row[1], a2 = row[2], a3 = row[3];
        float va[16] = {a0.x, a0.y, a0.z, a0.w, a1.x, a1.y, a1.z, a1.w,
                        a2.x, a2.y, a2.z, a2.w, a3.x, a3.y, a3.z, a3.w};
        float dotv = 0.f;
#pragma unroll
        for (int d = 0; d < 16; d++) dotv += sv[d * NO + lane] * va[d];
        tile[il][lane] = -dotv;
    }
    __syncthreads();

    // Transposed, coalesced store: 256B contiguous per (o, i-block)
    for (int idx = threadIdx.x; idx < IPB * NO; idx += 256) {
        int o = idx / IPB;
        int il = idx % IPB;
        g_losses[((size_t)(b * NO + o)) * NI + i0 + il] = tile[il][o];
    }
}

// ---------------------------------------------------------------------------
// Fused select + fixup: per (b,o) block.
//  round 1: full 256-bin histogram over 1152 keys -> bucket, compact matches
//  round 2: histogram over candidates only -> compact survivors (tiny set)
//  final:   exact rank-count among survivors -> threshold key
//  then:    rejected list (key > thrkey), gather those capsules, subtract
//           from pass-1 totals, write output. No rounds 3/4.
// ---------------------------------------------------------------------------
__global__ void __launch_bounds__(256) k_selectfix(const float* __restrict__ u,
                                                  float* __restrict__ out) {
    __shared__ unsigned skey[NI];
    __shared__ unsigned cand[NI];
    __shared__ unsigned cand2[NI];
    __shared__ int hist[256];
    __shared__ int srej[MAXREJ];
    __shared__ int scount, s_m1, s_m2;
    __shared__ int s_bucket, s_k;
    __shared__ unsigned s_thr;
    __shared__ float sred[8][17];
    __shared__ float stot[17];

    int b = blockIdx.x / NO;
    int o = blockIdx.x % NO;
    int tid = threadIdx.x;
    int w = tid >> 5, lane = tid & 31;

    // Load losses, convert to monotone unsigned keys
    const float* lp = &g_losses[((size_t)(b * NO + o)) * NI];
    for (int i = tid; i < NI; i += 256) {
        unsigned x = __float_as_uint(lp[i]);
        skey[i] = (x & 0x80000000u) ? ~x : (x | 0x80000000u);
    }
    if (tid == 0) { scount = 0; s_m1 = 0; s_m2 = 0; }
    if (tid < 256) hist[tid] = 0;
    __syncthreads();

    // ---- Round 1: histogram of top byte over all keys ----
    for (int i = tid; i < NI; i += 256) atomicAdd(&hist[skey[i] >> 24], 1);
    __syncthreads();
    if (tid < 32) {
        int base = lane * 8;
        int h[8];
        int seg = 0;
#pragma unroll
        for (int j = 0; j < 8; j++) { h[j] = hist[base + j]; seg += h[j]; }
        int incl = seg;
        for (int off = 1; off < 32; off <<= 1) {
            int n_ = __shfl_up_sync(0xffffffffu, incl, off);
            if (lane >= off) incl += n_;
        }
        int excl = incl - seg;
        int k = KSUB;
        bool has = (excl < k) && (excl + seg >= k);
        unsigned m = __ballot_sync(0xffffffffu, has);
        int src = __ffs(m) - 1;
        if (lane == src) {
            int run = excl;
#pragma unroll
            for (int j = 0; j < 8; j++) {
                if (run + h[j] >= k) { s_bucket = base + j; s_k = k - run; break; }
                run += h[j];
            }
        }
    }
    __syncthreads();
    unsigned bucket1 = (unsigned)s_bucket;
    int k1 = s_k;

    // compact round-1 matches; zero hist for round 2
    for (int i = tid; i < NI; i += 256) {
        unsigned key = skey[i];
        if ((key >> 24) == bucket1) cand[atomicAdd(&s_m1, 1)] = key;
    }
    if (tid < 256) hist[tid] = 0;
    __syncthreads();
    int m1 = s_m1;

    // ---- Round 2: histogram of byte 2 over candidates only ----
    for (int i = tid; i < m1; i += 256) atomicAdd(&hist[(cand[i] >> 16) & 255], 1);
    __syncthreads();
    if (tid < 32) {
        int base = lane * 8;
        int h[8];
        int seg = 0;
#pragma unroll
        for (int j = 0; j < 8; j++) { h[j] = hist[base + j]; seg += h[j]; }
        int incl = seg;
        for (int off = 1; off < 32; off <<= 1) {
            int n_ = __shfl_up_sync(0xffffffffu, incl, off);
            if (lane >= off) incl += n_;
        }
        int excl = incl - seg;
        int k = k1;
        bool has = (excl < k) && (excl + seg >= k);
        unsigned m = __ballot_sync(0xffffffffu, has);
        int src = __ffs(m) - 1;
        if (lane == src) {
            int run = excl;
#pragma unroll
            for (int j = 0; j < 8; j++) {
                if (run + h[j] >= k) { s_bucket = base + j; s_k = k - run; break; }
                run += h[j];
            }
        }
    }
    __syncthreads();
    unsigned bucket2 = (unsigned)s_bucket;
    int k2 = s_k;

    // compact round-2 survivors (expected tiny)
    for (int i = tid; i < m1; i += 256) {
        unsigned key = cand[i];
        if (((key >> 16) & 255) == bucket2) cand2[atomicAdd(&s_m2, 1)] = key;
    }
    __syncthreads();
    int m2 = s_m2;

    // ---- Final: exact k2-th smallest among survivors by rank counting ----
    for (int idx = tid; idx < m2; idx += 256) {
        unsigned kk = cand2[idx];
        int less = 0, leq = 0;
        for (int j = 0; j < m2; j++) {
            unsigned o2 = cand2[j];
            less += (o2 < kk);
            leq += (o2 <= kk);
        }
        if (less < k2 && leq >= k2) s_thr = kk;  // unique value; benign race on ties
    }
    __syncthreads();
    unsigned thrkey = s_thr;

    // Build rejected list: key strictly greater than the k-th smallest
    for (int i = tid; i < NI; i += 256) {
        if (skey[i] > thrkey) srej[atomicAdd(&scount, 1)] = i;
    }
    __syncthreads();
    int nr = scount;  // <= 230

    // Gather rejected capsules, accumulate u*n and n
    float acc[16];
    float aden = 0.f;
#pragma unroll
    for (int d = 0; d < 16; d++) acc[d] = 0.f;
    const float4* up = (const float4*)u + (size_t)b * NI * (NO * ND / 4);
    for (int r = tid; r < nr; r += 256) {
        int i = srej[r];
        const float4* row = up + (size_t)i * (NO * ND / 4) + o * (ND / 4);
        float4 a0 = row[0], a1 = row[1], a2 = row[2], a3 = row[3];
        float va[16] = {a0.x, a0.y, a0.z, a0.w, a1.x, a1.y, a1.z, a1.w,
                        a2.x, a2.y, a2.z, a2.w, a3.x, a3.y, a3.z, a3.w};
        float s = 0.f;
#pragma unroll
        for (int d = 0; d < 16; d++) s += va[d] * va[d];
        float n = sqrtf(s);
#pragma unroll
        for (int d = 0; d < 16; d++) acc[d] += va[d] * n;
        aden += n;
    }

    // Reduce 17 values across the block
#pragma unroll
    for (int t = 0; t < 17; t++) {
        float v = (t < 16) ? acc[t] : aden;
        for (int off = 16; off > 0; off >>= 1)
            v += __shfl_down_sync(0xffffffffu, v, off);
        if (lane == 0) sred[w][t] = v;
    }
    __syncthreads();
    if (tid < 17) {
        float s = 0.f;
#pragma unroll
        for (int ww = 0; ww < 8; ww++) s += sred[ww][tid];
        stot[tid] = s;
    }
    __syncthreads();
    if (tid < 16) {
        float den2 = g_den[b * NO + o] - stot[16];
        out[(b * NO + o) * ND + tid] =
            (g_num[(b * NO + o) * ND + tid] - stot[tid]) / den2;
    }
}

extern "C" void kernel_launch(void* const* d_in, const int* in_sizes, int n_in,
                              void* d_out, int out_size) {
    const float* u = (const float*)d_in[0];
    float* out = (float*)d_out;

    k_zero<<<(NB * NO * ND + 255) / 256, 256>>>();
    k_pass1<<<NB * CHUNKS, 256>>>(u);
    k_pass2<<<NB * CHUNKS, 256>>>(u);
    k_selectfix<<<NB * NO, 256>>>(u, out);
}

// round 7
// speedup vs baseline: 1.4786x; 1.4786x over previous
#include <cuda_runtime.h>
#include <math.h>

// Problem constants
#define NB 128
#define NI 1152
#define NO 32
#define ND 16
#define KSUB 922          // ceil(0.8 * 1152)
#define CHUNKS 9
#define IPB (NI / CHUNKS) // 128 i's per block
#define IPW (IPB / 8)     // 16 i's per warp (8 warps / block)
#define MAXREJ 232        // >= NI - KSUB = 230
#define KPL 36            // keys per lane: 1152/32

// Scratch (no allocation allowed -> __device__ globals)
__device__ float g_num[NB * NO * ND];
__device__ float g_den[NB * NO];
__device__ float g_losses[(size_t)NB * NO * NI]; // transposed: [b][o][i]

__global__ void k_zero() {
    int idx = blockIdx.x * blockDim.x + threadIdx.x;
    if (idx < NB * NO * ND) g_num[idx] = 0.f;
    if (idx < NB * NO)      g_den[idx] = 0.f;
}

// ---------------------------------------------------------------------------
// Pass 1: n = ||u||, num = sum_i u*n, den = sum_i n  (per b,o)
// One warp per (b,i); lane = o. Each lane reads its 64B capsule (4x LDG.128).
// ---------------------------------------------------------------------------
__global__ void __launch_bounds__(256) k_pass1(const float* __restrict__ u) {
    int b = blockIdx.x / CHUNKS;
    int chunk = blockIdx.x % CHUNKS;
    int w = threadIdx.x >> 5;
    int lane = threadIdx.x & 31;

    const float4* up = (const float4*)u + (size_t)b * NI * (NO * ND / 4);
    float acc[ND];
    float accden = 0.f;
#pragma unroll
    for (int d = 0; d < ND; d++) acc[d] = 0.f;

    int i0 = chunk * IPB + w * IPW;
    for (int ii = 0; ii < IPW; ii++) {
        const float4* row = up + (size_t)(i0 + ii) * (NO * ND / 4) + lane * (ND / 4);
        float4 a0 = row[0], a1 = row[1], a2 = row[2], a3 = row[3];
        float va[16] = {a0.x, a0.y, a0.z, a0.w, a1.x, a1.y, a1.z, a1.w,
                        a2.x, a2.y, a2.z, a2.w, a3.x, a3.y, a3.z, a3.w};
        float s = 0.f;
#pragma unroll
        for (int d = 0; d < 16; d++) s += va[d] * va[d];
        float n = sqrtf(s);
#pragma unroll
        for (int d = 0; d < 16; d++) acc[d] += va[d] * n;
        accden += n;
    }

    __shared__ float snum[8][NO * ND];
    __shared__ float sden[8][NO];
#pragma unroll
    for (int d = 0; d < ND; d++) snum[w][d * NO + lane] = acc[d];
    sden[w][lane] = accden;
    __syncthreads();

    for (int idx = threadIdx.x; idx < NO * ND; idx += 256) {
        int d = idx / NO, o = idx % NO;
        float s = 0.f;
#pragma unroll
        for (int ww = 0; ww < 8; ww++) s += snum[ww][idx];
        atomicAdd(&g_num[b * NO * ND + o * ND + d], s);
    }
    if (threadIdx.x < NO) {
        float s = 0.f;
#pragma unroll
        for (int ww = 0; ww < 8; ww++) s += sden[ww][threadIdx.x];
        atomicAdd(&g_den[b * NO + threadIdx.x], s);
    }
}

// ---------------------------------------------------------------------------
// Pass 2: losses[b,o,i] = -<v[b,o,:], u[b,i,o,:]>, v computed in-kernel.
// Stores TRANSPOSED [b][o][i] via padded smem tile for coalesced select reads.
// ---------------------------------------------------------------------------
__global__ void __launch_bounds__(256) k_pass2(const float* __restrict__ u) {
    __shared__ float sv[ND * NO];        // transposed: sv[d*NO + o]
    __shared__ float tile[IPB][NO + 1];  // [i_local][o], padded
    int b = blockIdx.x / CHUNKS;
    int chunk = blockIdx.x % CHUNKS;
    for (int idx = threadIdx.x; idx < NO * ND; idx += 256) {
        int o = idx / ND, d = idx % ND;
        sv[d * NO + o] = g_num[b * NO * ND + idx] / g_den[b * NO + o];
    }
    __syncthreads();

    int w = threadIdx.x >> 5;
    int lane = threadIdx.x & 31;
    const float4* up = (const float4*)u + (size_t)b * NI * (NO * ND / 4);
    int i0 = chunk * IPB;
    for (int ii = 0; ii < IPW; ii++) {
        int il = w * IPW + ii;
        const float4* row = up + (size_t)(i0 + il) * (NO * ND / 4) + lane * (ND / 4);
        float4 a0 = row[0], a1 = row[1], a2 = row[2], a3 = row[3];
        float va[16] = {a0.x, a0.y, a0.z, a0.w, a1.x, a1.y, a1.z, a1.w,
                        a2.x, a2.y, a2.z, a2.w, a3.x, a3.y, a3.z, a3.w};
        float dotv = 0.f;
#pragma unroll
        for (int d = 0; d < 16; d++) dotv += sv[d * NO + lane] * va[d];
        tile[il][lane] = -dotv;
    }
    __syncthreads();

    // Transposed, coalesced store: contiguous 512B per (o, i-block)
    for (int idx = threadIdx.x; idx < IPB * NO; idx += 256) {
        int o = idx >> 7;        // idx / 128
        int il = idx & 127;      // idx % 128
        g_losses[((size_t)(b * NO + o)) * NI + i0 + il] = tile[il][o];
    }
}

// ---------------------------------------------------------------------------
// Fused select + fixup, ONE WARP per (b,o). Keys live in registers (36/lane).
// 4-round radix select via warp-private smem histogram (no __syncthreads),
// then gather the <=230 rejected capsules (4 lanes per capsule, LDG.128)
// and subtract from pass-1 totals. Lanes 0-3 write the output float4s.
// ---------------------------------------------------------------------------
__global__ void __launch_bounds__(256) k_selectfix(const float* __restrict__ u,
                                                  float* __restrict__ out) {
    __shared__ int hist[8][256];
    __shared__ int wcount[8];
    __shared__ int wlist[8][MAXREJ];

    int w = threadIdx.x >> 5, lane = threadIdx.x & 31;
    int bo = blockIdx.x * 8 + w;
    int b = bo >> 5, o = bo & 31;

    // Load this (b,o)'s 1152 losses as monotone unsigned keys (coalesced)
    unsigned key[KPL];
    const float* lp = &g_losses[(size_t)bo * NI];
#pragma unroll
    for (int j = 0; j < KPL; j++) {
        unsigned x = __float_as_uint(lp[j * 32 + lane]);
        key[j] = (x & 0x80000000u) ? ~x : (x | 0x80000000u);
    }
    if (lane == 0) wcount[w] = 0;

    // 4-round MSB-first radix select (warp-private, shfl scan, no block sync)
    unsigned prefix = 0;
    int k = KSUB;
#pragma unroll
    for (int shift = 24; shift >= 0; shift -= 8) {
#pragma unroll
        for (int t = 0; t < 8; t++) hist[w][lane * 8 + t] = 0;
        __syncwarp();
#pragma unroll
        for (int j = 0; j < KPL; j++) {
            unsigned kk = key[j];
            bool match = (shift == 24) || ((kk >> (shift + 8)) == prefix);
            if (match) atomicAdd(&hist[w][(kk >> shift) & 255], 1);
        }
        __syncwarp();
        int h[8], seg = 0;
#pragma unroll
        for (int t = 0; t < 8; t++) { h[t] = hist[w][lane * 8 + t]; seg += h[t]; }
        int incl = seg;
#pragma unroll
        for (int off = 1; off < 32; off <<= 1) {
            int n_ = __shfl_up_sync(0xffffffffu, incl, off);
            if (lane >= off) incl += n_;
        }
        int excl = incl - seg;
        bool has = (excl < k) && (excl + seg >= k);
        unsigned mba = __ballot_sync(0xffffffffu, has);
        int src = __ffs(mba) - 1;
        int bsel = 0, kk2 = 0;
        if (lane == src) {
            int run = excl;
#pragma unroll
            for (int t = 0; t < 8; t++) {
                if (run + h[t] >= k) { bsel = lane * 8 + t; kk2 = k - run; break; }
                run += h[t];
            }
        }
        bsel = __shfl_sync(0xffffffffu, bsel, src);
        k = __shfl_sync(0xffffffffu, kk2, src);
        prefix = (prefix << 8) | (unsigned)bsel;
        __syncwarp();
    }
    unsigned thrkey = prefix;  // exact k-th smallest key

    // Rejected list (key strictly greater -> loss > kth) ; nr <= 230
#pragma unroll
    for (int j = 0; j < KPL; j++) {
        if (key[j] > thrkey) {
            int p = atomicAdd(&wcount[w], 1);
            wlist[w][p] = j * 32 + lane;
        }
    }
    __syncwarp();
    int nr = wcount[w];

    // Gather rejected capsules: 4 lanes per capsule (one LDG.128 each)
    int p = lane & 3, g = lane >> 2;
    const float4* up = (const float4*)u + (size_t)b * NI * 128 + o * 4 + p;
    float acc0 = 0.f, acc1 = 0.f, acc2 = 0.f, acc3 = 0.f, aden = 0.f;
    int nrp = (nr + 7) & ~7;
    for (int t = g; t < nrp; t += 8) {
        bool valid = t < nr;
        int i = valid ? wlist[w][t] : 0;
        float4 a = up[(size_t)i * 128];
        if (!valid) { a.x = 0.f; a.y = 0.f; a.z = 0.f; a.w = 0.f; }
        float s = a.x * a.x + a.y * a.y + a.z * a.z + a.w * a.w;
        s += __shfl_xor_sync(0xffffffffu, s, 1);
        s += __shfl_xor_sync(0xffffffffu, s, 2);
        float n = sqrtf(s);
        acc0 += a.x * n; acc1 += a.y * n; acc2 += a.z * n; acc3 += a.w * n;
        if (p == 0) aden += n;
    }
    // Reduce across the 8 capsule-groups (offsets 4,8,16 preserve p)
#pragma unroll
    for (int off = 4; off < 32; off <<= 1) {
        acc0 += __shfl_xor_sync(0xffffffffu, acc0, off);
        acc1 += __shfl_xor_sync(0xffffffffu, acc1, off);
        acc2 += __shfl_xor_sync(0xffffffffu, acc2, off);
        acc3 += __shfl_xor_sync(0xffffffffu, acc3, off);
    }
    // Full reduce for aden (non-p0 lanes hold 0)
#pragma unroll
    for (int off = 1; off < 32; off <<= 1)
        aden += __shfl_xor_sync(0xffffffffu, aden, off);

    if (lane < 4) {
        float4 nm = ((const float4*)g_num)[bo * 4 + lane];
        float den2 = g_den[bo] - aden;
        float4 r;
        r.x = (nm.x - acc0) / den2;
        r.y = (nm.y - acc1) / den2;
        r.z = (nm.z - acc2) / den2;
        r.w = (nm.w - acc3) / den2;
        ((float4*)out)[bo * 4 + lane] = r;
    }
}

extern "C" void kernel_launch(void* const* d_in, const int* in_sizes, int n_in,
                              void* d_out, int out_size) {
    const float* u = (const float*)d_in[0];
    float* out = (float*)d_out;

    k_zero<<<(NB * NO * ND + 255) / 256, 256>>>();
    k_pass1<<<NB * CHUNKS, 256>>>(u);
    k_pass2<<<NB * CHUNKS, 256>>>(u);
    k_selectfix<<<NB * NO / 8, 256>>>(u, out);
}

// round 8
// speedup vs baseline: 1.6447x; 1.1123x over previous
#include <cuda_runtime.h>
#include <math.h>

// Problem constants
#define NB 128
#define NI 1152
#define NO 32
#define ND 16
#define KSUB 922          // ceil(0.8 * 1152)
#define CHUNKS 9
#define IPB (NI / CHUNKS) // 128 i's per block
#define IPW (IPB / 8)     // 16 i's per warp (8 warps / block)
#define MAXREJ 232        // >= NI - KSUB = 230
#define KPL 36            // keys per lane: 1152/32

// Scratch (no allocation allowed -> __device__ globals)
__device__ float g_num[NB * NO * ND];
__device__ float g_den[NB * NO];
__device__ float g_losses[(size_t)NB * NO * NI]; // transposed: [b][o][i]

__global__ void k_zero() {
    int idx = blockIdx.x * blockDim.x + threadIdx.x;
    if (idx < NB * NO * ND) g_num[idx] = 0.f;
    if (idx < NB * NO)      g_den[idx] = 0.f;
}

// ---------------------------------------------------------------------------
// Pass 1: n = ||u||, num = sum_i u*n, den = sum_i n  (per b,o)
// One warp per (b,i); lane = o. Each lane reads its 64B capsule (4x LDG.128).
// ---------------------------------------------------------------------------
__global__ void __launch_bounds__(256) k_pass1(const float* __restrict__ u) {
    int b = blockIdx.x / CHUNKS;
    int chunk = blockIdx.x % CHUNKS;
    int w = threadIdx.x >> 5;
    int lane = threadIdx.x & 31;

    const float4* up = (const float4*)u + (size_t)b * NI * (NO * ND / 4);
    float acc[ND];
    float accden = 0.f;
#pragma unroll
    for (int d = 0; d < ND; d++) acc[d] = 0.f;

    int i0 = chunk * IPB + w * IPW;
#pragma unroll 2
    for (int ii = 0; ii < IPW; ii++) {
        const float4* row = up + (size_t)(i0 + ii) * (NO * ND / 4) + lane * (ND / 4);
        float4 a0 = row[0], a1 = row[1], a2 = row[2], a3 = row[3];
        float va[16] = {a0.x, a0.y, a0.z, a0.w, a1.x, a1.y, a1.z, a1.w,
                        a2.x, a2.y, a2.z, a2.w, a3.x, a3.y, a3.z, a3.w};
        float s = 0.f;
#pragma unroll
        for (int d = 0; d < 16; d++) s += va[d] * va[d];
        float n = sqrtf(s);
#pragma unroll
        for (int d = 0; d < 16; d++) acc[d] += va[d] * n;
        accden += n;
    }

    __shared__ float snum[8][NO * ND];
    __shared__ float sden[8][NO];
#pragma unroll
    for (int d = 0; d < ND; d++) snum[w][d * NO + lane] = acc[d];
    sden[w][lane] = accden;
    __syncthreads();

    for (int idx = threadIdx.x; idx < NO * ND; idx += 256) {
        int d = idx / NO, o = idx % NO;
        float s = 0.f;
#pragma unroll
        for (int ww = 0; ww < 8; ww++) s += snum[ww][idx];
        atomicAdd(&g_num[b * NO * ND + o * ND + d], s);
    }
    if (threadIdx.x < NO) {
        float s = 0.f;
#pragma unroll
        for (int ww = 0; ww < 8; ww++) s += sden[ww][threadIdx.x];
        atomicAdd(&g_den[b * NO + threadIdx.x], s);
    }
}

// ---------------------------------------------------------------------------
// Pass 2: losses[b,o,i] = -<v[b,o,:], u[b,i,o,:]>, v computed in-kernel.
// Stores TRANSPOSED [b][o][i] via padded smem tile for coalesced select reads.
// ---------------------------------------------------------------------------
__global__ void __launch_bounds__(256) k_pass2(const float* __restrict__ u) {
    __shared__ float sv[ND * NO];        // transposed: sv[d*NO + o]
    __shared__ float tile[IPB][NO + 1];  // [i_local][o], padded
    int b = blockIdx.x / CHUNKS;
    int chunk = blockIdx.x % CHUNKS;
    for (int idx = threadIdx.x; idx < NO * ND; idx += 256) {
        int o = idx / ND, d = idx % ND;
        sv[d * NO + o] = g_num[b * NO * ND + idx] / g_den[b * NO + o];
    }
    __syncthreads();

    int w = threadIdx.x >> 5;
    int lane = threadIdx.x & 31;
    const float4* up = (const float4*)u + (size_t)b * NI * (NO * ND / 4);
    int i0 = chunk * IPB;
#pragma unroll 2
    for (int ii = 0; ii < IPW; ii++) {
        int il = w * IPW + ii;
        const float4* row = up + (size_t)(i0 + il) * (NO * ND / 4) + lane * (ND / 4);
        float4 a0 = row[0], a1 = row[1], a2 = row[2], a3 = row[3];
        float va[16] = {a0.x, a0.y, a0.z, a0.w, a1.x, a1.y, a1.z, a1.w,
                        a2.x, a2.y, a2.z, a2.w, a3.x, a3.y, a3.z, a3.w};
        float dotv = 0.f;
#pragma unroll
        for (int d = 0; d < 16; d++) dotv += sv[d * NO + lane] * va[d];
        tile[il][lane] = -dotv;
    }
    __syncthreads();

    // Transposed, coalesced store: contiguous 512B per (o, i-block)
    for (int idx = threadIdx.x; idx < IPB * NO; idx += 256) {
        int o = idx >> 7;        // idx / 128
        int il = idx & 127;      // idx % 128
        g_losses[((size_t)(b * NO + o)) * NI + i0 + il] = tile[il][o];
    }
}

// ---------------------------------------------------------------------------
// Fused select + fixup, ONE WARP per (b,o). Keys in SHARED memory (low regs,
// high occupancy). 4-round radix select via warp-private smem histogram
// (no __syncthreads), then gather the <=230 rejected capsules (4 lanes per
// capsule, LDG.128) and subtract from pass-1 totals. Lanes 0-3 write output.
// ---------------------------------------------------------------------------
__global__ void __launch_bounds__(256) k_selectfix(const float* __restrict__ u,
                                                  float* __restrict__ out) {
    __shared__ unsigned skey[8][NI];   // 36864 B
    __shared__ int hist[8][256];       //  8192 B
    __shared__ short wlist[8][MAXREJ]; //  3712 B
    __shared__ int wcount[8];          //    32 B  (total 48800 < 48KB limit)

    int w = threadIdx.x >> 5, lane = threadIdx.x & 31;
    int bo = blockIdx.x * 8 + w;
    int b = bo >> 5, o = bo & 31;

    // Load this (b,o)'s 1152 losses as monotone unsigned keys (coalesced)
    const float* lp = &g_losses[(size_t)bo * NI];
#pragma unroll 4
    for (int j = 0; j < KPL; j++) {
        unsigned x = __float_as_uint(lp[j * 32 + lane]);
        skey[w][j * 32 + lane] = (x & 0x80000000u) ? ~x : (x | 0x80000000u);
    }
    if (lane == 0) wcount[w] = 0;
    __syncwarp();

    // 4-round MSB-first radix select (warp-private, shfl scan, no block sync)
    unsigned prefix = 0;
    int k = KSUB;
#pragma unroll
    for (int shift = 24; shift >= 0; shift -= 8) {
#pragma unroll
        for (int t = 0; t < 8; t++) hist[w][lane * 8 + t] = 0;
        __syncwarp();
#pragma unroll 4
        for (int j = 0; j < KPL; j++) {
            unsigned kk = skey[w][j * 32 + lane];
            bool match = (shift == 24) || ((kk >> (shift + 8)) == prefix);
            if (match) atomicAdd(&hist[w][(kk >> shift) & 255], 1);
        }
        __syncwarp();
        int h[8], seg = 0;
#pragma unroll
        for (int t = 0; t < 8; t++) { h[t] = hist[w][lane * 8 + t]; seg += h[t]; }
        int incl = seg;
#pragma unroll
        for (int off = 1; off < 32; off <<= 1) {
            int n_ = __shfl_up_sync(0xffffffffu, incl, off);
            if (lane >= off) incl += n_;
        }
        int excl = incl - seg;
        bool has = (excl < k) && (excl + seg >= k);
        unsigned mba = __ballot_sync(0xffffffffu, has);
        int src = __ffs(mba) - 1;
        int bsel = 0, kk2 = 0;
        if (lane == src) {
            int run = excl;
#pragma unroll
            for (int t = 0; t < 8; t++) {
                if (run + h[t] >= k) { bsel = lane * 8 + t; kk2 = k - run; break; }
                run += h[t];
            }
        }
        bsel = __shfl_sync(0xffffffffu, bsel, src);
        k = __shfl_sync(0xffffffffu, kk2, src);
        prefix = (prefix << 8) | (unsigned)bsel;
        __syncwarp();
    }
    unsigned thrkey = prefix;  // exact k-th smallest key

    // Rejected list (key strictly greater -> loss > kth) ; nr <= 230
#pragma unroll 4
    for (int j = 0; j < KPL; j++) {
        unsigned kk = skey[w][j * 32 + lane];
        if (kk > thrkey) {
            int p = atomicAdd(&wcount[w], 1);
            wlist[w][p] = (short)(j * 32 + lane);
        }
    }
    __syncwarp();
    int nr = wcount[w];

    // Gather rejected capsules: 4 lanes per capsule (one LDG.128 each)
    int p = lane & 3, g = lane >> 2;
    const float4* up = (const float4*)u + (size_t)b * NI * 128 + o * 4 + p;
    float acc0 = 0.f, acc1 = 0.f, acc2 = 0.f, acc3 = 0.f, aden = 0.f;
    int nrp = (nr + 7) & ~7;
#pragma unroll 2
    for (int t = g; t < nrp; t += 8) {
        bool valid = t < nr;
        int i = valid ? (int)wlist[w][t] : 0;
        float4 a = up[(size_t)i * 128];
        if (!valid) { a.x = 0.f; a.y = 0.f; a.z = 0.f; a.w = 0.f; }
        float s = a.x * a.x + a.y * a.y + a.z * a.z + a.w * a.w;
        s += __shfl_xor_sync(0xffffffffu, s, 1);
        s += __shfl_xor_sync(0xffffffffu, s, 2);
        float n = sqrtf(s);
        acc0 += a.x * n; acc1 += a.y * n; acc2 += a.z * n; acc3 += a.w * n;
        if (p == 0) aden += n;
    }
    // Reduce across the 8 capsule-groups (offsets 4,8,16 preserve p)
#pragma unroll
    for (int off = 4; off < 32; off <<= 1) {
        acc0 += __shfl_xor_sync(0xffffffffu, acc0, off);
        acc1 += __shfl_xor_sync(0xffffffffu, acc1, off);
        acc2 += __shfl_xor_sync(0xffffffffu, acc2, off);
        acc3 += __shfl_xor_sync(0xffffffffu, acc3, off);
    }
    // Full reduce for aden (non-p0 lanes hold 0)
#pragma unroll
    for (int off = 1; off < 32; off <<= 1)
        aden += __shfl_xor_sync(0xffffffffu, aden, off);

    if (lane < 4) {
        float4 nm = ((const float4*)g_num)[bo * 4 + lane];
        float den2 = g_den[bo] - aden;
        float4 r;
        r.x = (nm.x - acc0) / den2;
        r.y = (nm.y - acc1) / den2;
        r.z = (nm.z - acc2) / den2;
        r.w = (nm.w - acc3) / den2;
        ((float4*)out)[bo * 4 + lane] = r;
    }
}

extern "C" void kernel_launch(void* const* d_in, const int* in_sizes, int n_in,
                              void* d_out, int out_size) {
    const float* u = (const float*)d_in[0];
    float* out = (float*)d_out;

    k_zero<<<(NB * NO * ND + 255) / 256, 256>>>();
    k_pass1<<<NB * CHUNKS, 256>>>(u);
    k_pass2<<<NB * CHUNKS, 256>>>(u);
    k_selectfix<<<NB * NO / 8, 256>>>(u, out);
}